// round 4
// baseline (speedup 1.0000x reference)
#include <cuda_runtime.h>

// ElementwiseTensorProd_o1: l=1 outputs of per-channel tensor product.
//   p01_m = s_l * v_r[m]
//   p10_m = v_l[m] * s_r
//   p11_m = cross(v_l, v_r)[m] * (1/sqrt(2))
// Layout: inputs z0 (N,RANK), z1 (N,3,RANK); out (N,3,3*RANK) = [p01|p10|p11].
// DRAM-roofline streaming kernel. R4: persistent single-wave grid-stride
// launch (148 SMs x 8 blocks) to eliminate wave-transition DRAM-demand dips.

#define RANK 256
#define RQ   (RANK / 4)      // 64 float4 groups per rank row
#define OQ   (3 * RANK / 4)  // 192 float4 groups per output row

#define NSM        148
#define BLK_PER_SM 8
#define THREADS    256

__device__ __forceinline__ float4 mul4(float4 a, float4 b) {
    return make_float4(a.x * b.x, a.y * b.y, a.z * b.z, a.w * b.w);
}
__device__ __forceinline__ float4 fms4(float4 a, float4 b, float4 c, float4 d, float s) {
    return make_float4((a.x * b.x - c.x * d.x) * s,
                       (a.y * b.y - c.y * d.y) * s,
                       (a.z * b.z - c.z * d.z) * s,
                       (a.w * b.w - c.w * d.w) * s);
}

__global__ void __launch_bounds__(THREADS)
etp_o1_kernel(const float4* __restrict__ z0l,
              const float4* __restrict__ z1l,
              const float4* __restrict__ z0r,
              const float4* __restrict__ z1r,
              float4* __restrict__ out,
              int n_total)  // N * RQ
{
    const float INV_SQRT2 = 0.7071067811865476f;
    const int stride = gridDim.x * blockDim.x;

    for (int idx = blockIdx.x * blockDim.x + threadIdx.x; idx < n_total; idx += stride) {
        int n = idx >> 6;          // / RQ
        int r = idx & (RQ - 1);    // % RQ

        // Front-batched streaming loads (8x LDG.128, evict-first)
        const float4* vl = z1l + (size_t)(n * 3) * RQ + r;
        const float4* vr = z1r + (size_t)(n * 3) * RQ + r;
        float4 sl  = __ldcs(z0l + (size_t)n * RQ + r);
        float4 sr  = __ldcs(z0r + (size_t)n * RQ + r);
        float4 vl0 = __ldcs(vl + 0 * RQ);
        float4 vl1 = __ldcs(vl + 1 * RQ);
        float4 vl2 = __ldcs(vl + 2 * RQ);
        float4 vr0 = __ldcs(vr + 0 * RQ);
        float4 vr1 = __ldcs(vr + 1 * RQ);
        float4 vr2 = __ldcs(vr + 2 * RQ);

        float4* ob = out + (size_t)(n * 3) * OQ + r;

        // m = 0
        __stcs(ob + 0 * OQ + 0 * RQ, mul4(sl, vr0));
        __stcs(ob + 0 * OQ + 1 * RQ, mul4(vl0, sr));
        __stcs(ob + 0 * OQ + 2 * RQ, fms4(vl1, vr2, vl2, vr1, INV_SQRT2));
        // m = 1
        __stcs(ob + 1 * OQ + 0 * RQ, mul4(sl, vr1));
        __stcs(ob + 1 * OQ + 1 * RQ, mul4(vl1, sr));
        __stcs(ob + 1 * OQ + 2 * RQ, fms4(vl2, vr0, vl0, vr2, INV_SQRT2));
        // m = 2
        __stcs(ob + 2 * OQ + 0 * RQ, mul4(sl, vr2));
        __stcs(ob + 2 * OQ + 1 * RQ, mul4(vl2, sr));
        __stcs(ob + 2 * OQ + 2 * RQ, fms4(vl0, vr1, vl1, vr0, INV_SQRT2));
    }
}

extern "C" void kernel_launch(void* const* d_in, const int* in_sizes, int n_in,
                              void* d_out, int out_size) {
    const float4* z0l = (const float4*)d_in[0];
    const float4* z1l = (const float4*)d_in[1];
    const float4* z0r = (const float4*)d_in[2];
    const float4* z1r = (const float4*)d_in[3];
    float4* out = (float4*)d_out;

    int N = in_sizes[0] / RANK;          // 50000
    int n_total = N * RQ;                // 3.2M float4-work-items
    int blocks = NSM * BLK_PER_SM;       // single persistent wave
    etp_o1_kernel<<<blocks, THREADS>>>(z0l, z1l, z0r, z1r, out, n_total);
}

// round 5
// speedup vs baseline: 1.0389x; 1.0389x over previous
#include <cuda_runtime.h>

// ElementwiseTensorProd_o1: l=1 outputs of per-channel tensor product.
//   p01_m = s_l * v_r[m]
//   p10_m = v_l[m] * s_r
//   p11_m = cross(v_l, v_r)[m] * (1/sqrt(2))
// Layout: inputs z0 (N,RANK), z1 (N,3,RANK); out (N,3,3*RANK) = [p01|p10|p11].
// R5: 256-bit (v8.f32) global loads/stores — Blackwell LDG.E.256/STG.E.256 —
// flat single-row-per-thread launch, streaming (cs) policy.

#define RANK 256
#define R8   (RANK / 8)      // 32 v8 groups per rank row
#define V8_BYTES 32

struct V8 { float v[8]; };

__device__ __forceinline__ V8 ld8(const float* p) {
    V8 r;
    asm volatile("ld.global.cs.v8.f32 {%0,%1,%2,%3,%4,%5,%6,%7}, [%8];"
                 : "=f"(r.v[0]), "=f"(r.v[1]), "=f"(r.v[2]), "=f"(r.v[3]),
                   "=f"(r.v[4]), "=f"(r.v[5]), "=f"(r.v[6]), "=f"(r.v[7])
                 : "l"(p));
    return r;
}
__device__ __forceinline__ void st8(float* p, const V8& a) {
    asm volatile("st.global.cs.v8.f32 [%0], {%1,%2,%3,%4,%5,%6,%7,%8};"
                 :: "l"(p),
                    "f"(a.v[0]), "f"(a.v[1]), "f"(a.v[2]), "f"(a.v[3]),
                    "f"(a.v[4]), "f"(a.v[5]), "f"(a.v[6]), "f"(a.v[7])
                 : "memory");
}

__device__ __forceinline__ V8 mul8(const V8& a, const V8& b) {
    V8 r;
#pragma unroll
    for (int i = 0; i < 8; i++) r.v[i] = a.v[i] * b.v[i];
    return r;
}
__device__ __forceinline__ V8 fms8(const V8& a, const V8& b, const V8& c, const V8& d, float s) {
    V8 r;
#pragma unroll
    for (int i = 0; i < 8; i++) r.v[i] = (a.v[i] * b.v[i] - c.v[i] * d.v[i]) * s;
    return r;
}

__global__ void __launch_bounds__(256)
etp_o1_kernel(const float* __restrict__ z0l,
              const float* __restrict__ z1l,
              const float* __restrict__ z0r,
              const float* __restrict__ z1r,
              float* __restrict__ out,
              int n_total)  // N * R8
{
    const float INV_SQRT2 = 0.7071067811865476f;
    int idx = blockIdx.x * blockDim.x + threadIdx.x;
    if (idx >= n_total) return;

    int n = idx >> 5;           // / R8
    int r = idx & (R8 - 1);     // % R8
    int c = r * 8;              // float offset within rank row

    // Front-batched 256-bit streaming loads (8x LDG.E.256 = 2KB/thread)
    const float* vl = z1l + (size_t)(n * 3) * RANK + c;
    const float* vr = z1r + (size_t)(n * 3) * RANK + c;
    V8 sl  = ld8(z0l + (size_t)n * RANK + c);
    V8 sr  = ld8(z0r + (size_t)n * RANK + c);
    V8 vl0 = ld8(vl + 0 * RANK);
    V8 vl1 = ld8(vl + 1 * RANK);
    V8 vl2 = ld8(vl + 2 * RANK);
    V8 vr0 = ld8(vr + 0 * RANK);
    V8 vr1 = ld8(vr + 1 * RANK);
    V8 vr2 = ld8(vr + 2 * RANK);

    // Output: (N, 3, 3*RANK); path p of row m at (n*3+m)*3*RANK + p*RANK + c
    float* ob = out + (size_t)(n * 3) * (3 * RANK) + c;

    // m = 0
    st8(ob + 0 * (3 * RANK) + 0 * RANK, mul8(sl, vr0));
    st8(ob + 0 * (3 * RANK) + 1 * RANK, mul8(vl0, sr));
    st8(ob + 0 * (3 * RANK) + 2 * RANK, fms8(vl1, vr2, vl2, vr1, INV_SQRT2));
    // m = 1
    st8(ob + 1 * (3 * RANK) + 0 * RANK, mul8(sl, vr1));
    st8(ob + 1 * (3 * RANK) + 1 * RANK, mul8(vl1, sr));
    st8(ob + 1 * (3 * RANK) + 2 * RANK, fms8(vl2, vr0, vl0, vr2, INV_SQRT2));
    // m = 2
    st8(ob + 2 * (3 * RANK) + 0 * RANK, mul8(sl, vr2));
    st8(ob + 2 * (3 * RANK) + 1 * RANK, mul8(vl2, sr));
    st8(ob + 2 * (3 * RANK) + 2 * RANK, fms8(vl0, vr1, vl1, vr0, INV_SQRT2));
}

extern "C" void kernel_launch(void* const* d_in, const int* in_sizes, int n_in,
                              void* d_out, int out_size) {
    const float* z0l = (const float*)d_in[0];
    const float* z1l = (const float*)d_in[1];
    const float* z0r = (const float*)d_in[2];
    const float* z1r = (const float*)d_in[3];
    float* out = (float*)d_out;

    int N = in_sizes[0] / RANK;          // 50000
    int n_total = N * R8;                // 1.6M v8-work-items
    int threads = 256;
    int blocks = (n_total + threads - 1) / threads;
    etp_o1_kernel<<<blocks, threads>>>(z0l, z1l, z0r, z1r, out, n_total);
}

// round 6
// speedup vs baseline: 1.0522x; 1.0128x over previous
#include <cuda_runtime.h>

// ElementwiseTensorProd_o1: l=1 outputs of per-channel tensor product.
//   p01_m = s_l * v_r[m]
//   p10_m = v_l[m] * s_r
//   p11_m = cross(v_l, v_r)[m] * (1/sqrt(2))
// Layout: inputs z0 (N,RANK), z1 (N,3,RANK); out (N,3,3*RANK) = [p01|p10|p11].
// R6: block-phased R/W bursts — __syncthreads() between the block's load
// phase and store phase lengthens same-direction DRAM bursts (targets
// read/write bus-turnaround, the measured binder at ~84% of HBM spec).

#define RANK 256
#define RQ   (RANK / 4)      // 64 float4 groups per rank row
#define OQ   (3 * RANK / 4)  // 192 float4 groups per output row

__device__ __forceinline__ float4 mul4(float4 a, float4 b) {
    return make_float4(a.x * b.x, a.y * b.y, a.z * b.z, a.w * b.w);
}
__device__ __forceinline__ float4 fms4(float4 a, float4 b, float4 c, float4 d, float s) {
    return make_float4((a.x * b.x - c.x * d.x) * s,
                       (a.y * b.y - c.y * d.y) * s,
                       (a.z * b.z - c.z * d.z) * s,
                       (a.w * b.w - c.w * d.w) * s);
}

__global__ void __launch_bounds__(256)
etp_o1_kernel(const float4* __restrict__ z0l,
              const float4* __restrict__ z1l,
              const float4* __restrict__ z0r,
              const float4* __restrict__ z1r,
              float4* __restrict__ out,
              int n_total)  // N * RQ
{
    const float INV_SQRT2 = 0.7071067811865476f;
    int idx = blockIdx.x * blockDim.x + threadIdx.x;
    bool active = (idx < n_total);
    if (!active) idx = n_total - 1;   // clamp: keep whole block in the barrier

    int n = idx >> 6;          // / RQ
    int r = idx & (RQ - 1);    // % RQ

    // ---- Load phase: whole block issues all 8 LDG.128 before any STG ----
    const float4* vl = z1l + (size_t)(n * 3) * RQ + r;
    const float4* vr = z1r + (size_t)(n * 3) * RQ + r;
    float4 sl  = __ldcs(z0l + (size_t)n * RQ + r);
    float4 sr  = __ldcs(z0r + (size_t)n * RQ + r);
    float4 vl0 = __ldcs(vl + 0 * RQ);
    float4 vl1 = __ldcs(vl + 1 * RQ);
    float4 vl2 = __ldcs(vl + 2 * RQ);
    float4 vr0 = __ldcs(vr + 0 * RQ);
    float4 vr1 = __ldcs(vr + 1 * RQ);
    float4 vr2 = __ldcs(vr + 2 * RQ);

    // Cohort the phases: no warp starts its store burst until every warp
    // in the block has issued its load burst (orders issue only; per-warp
    // scoreboards still hide the load latency at the consuming FMUL).
    __syncthreads();

    if (!active) return;

    // ---- Store phase: 9x STG.128 burst ----
    float4* ob = out + (size_t)(n * 3) * OQ + r;

    // m = 0
    __stcs(ob + 0 * OQ + 0 * RQ, mul4(sl, vr0));
    __stcs(ob + 0 * OQ + 1 * RQ, mul4(vl0, sr));
    __stcs(ob + 0 * OQ + 2 * RQ, fms4(vl1, vr2, vl2, vr1, INV_SQRT2));
    // m = 1
    __stcs(ob + 1 * OQ + 0 * RQ, mul4(sl, vr1));
    __stcs(ob + 1 * OQ + 1 * RQ, mul4(vl1, sr));
    __stcs(ob + 1 * OQ + 2 * RQ, fms4(vl2, vr0, vl0, vr2, INV_SQRT2));
    // m = 2
    __stcs(ob + 2 * OQ + 0 * RQ, mul4(sl, vr2));
    __stcs(ob + 2 * OQ + 1 * RQ, mul4(vl2, sr));
    __stcs(ob + 2 * OQ + 2 * RQ, fms4(vl0, vr1, vl1, vr0, INV_SQRT2));
}

extern "C" void kernel_launch(void* const* d_in, const int* in_sizes, int n_in,
                              void* d_out, int out_size) {
    const float4* z0l = (const float4*)d_in[0];
    const float4* z1l = (const float4*)d_in[1];
    const float4* z0r = (const float4*)d_in[2];
    const float4* z1r = (const float4*)d_in[3];
    float4* out = (float4*)d_out;

    int N = in_sizes[0] / RANK;          // 50000
    int n_total = N * RQ;                // 3.2M float4-work-items
    int threads = 256;
    int blocks = (n_total + threads - 1) / threads;
    etp_o1_kernel<<<blocks, threads>>>(z0l, z1l, z0r, z1r, out, n_total);
}